// round 12
// baseline (speedup 1.0000x reference)
#include <cuda_runtime.h>
#include <cstdint>

// ---------------- problem constants ----------------
#define L_      13689           // LH*LW
#define LPAD    13696           // 107 * 128
#define D_      3072            // C*KH*KW
#define NMEM    4096
#define HH      128
#define WW      128
#define CC      3
#define KHH     32
#define KWW     32
#define PADP    10
#define LHH     117
#define LWW     117

// ---------------- GEMM tiling (mma.sync s8, m16n8k32) ----------------
#define TM      128              // CTA M
#define TNB     128              // CTA N
#define NT      (NMEM / TNB)     // 32 N-tiles
#define TK      128              // K int8 elements per stage (4 k32 slices)
#define NKT     (D_ / TK)        // 24
#define AROW    144              // bytes per smem row: 128 int8 + 16B pad
#define ASTG    (TM * AROW)      // 18432
#define BSTG    (TNB * AROW)     // 18432
#define STG     (ASTG + BSTG)    // 36864
#define SMEM_GEMM (3 * STG)      // 110592 (3 stages) -> 2 CTAs/SM

// quantization: A = round(v*127) (v in [0,1)); B = round(m*127/6), clamp +-127
#define QB      (127.0f / 6.0f)
#define RECON   (6.0f / (127.0f * 127.0f))
#define MARGIN  3.5f
#define CMAX    16

typedef unsigned long long ull;

// ---------------- static device scratch ----------------
__device__ __align__(16) int8_t g_Aq[(size_t)LPAD * D_];            // 42 MB
__device__ __align__(16) int8_t g_Bq[(size_t)NMEM * D_];            // 12.6 MB
__device__ __align__(16) float  g_bias[NMEM];                       // -0.5*||mem_n||^2 exact
__device__ __align__(16) float  g_scores[(size_t)LPAD * NMEM];      // 224 MB
__device__ __align__(16) float g_t1v[(size_t)LPAD * NT];            // per (row, tile) top1 val
__device__ __align__(16) int   g_t1i[(size_t)LPAD * NT];            // top1 idx (global n)
__device__ __align__(16) float g_t2v[(size_t)LPAD * NT];            // top2 val
__device__ int   g_cand[(size_t)L_ * CMAX];
__device__ int   g_candcnt[L_];
__device__ int   g_pid[L_];
__device__ float g_facc[CC * HH * WW];
__device__ unsigned int g_maxkey;

// ---------------- helpers ----------------
__device__ __forceinline__ uint32_t smem_u32(const void* p) {
    uint32_t a;
    asm("{ .reg .u64 t; cvta.to.shared.u64 t, %1; cvt.u32.u64 %0, t; }" : "=r"(a) : "l"(p));
    return a;
}
__device__ __forceinline__ void cp16(uint32_t smem_dst, const void* gsrc) {
    asm volatile("cp.async.cg.shared.global [%0], [%1], 16;" :: "r"(smem_dst), "l"(gsrc));
}
__device__ __forceinline__ void cp_commit() { asm volatile("cp.async.commit_group;"); }
template <int N> __device__ __forceinline__ void cp_wait() {
    asm volatile("cp.async.wait_group %0;" :: "n"(N));
}
// top-2 update; strict > keeps earliest (lowest n) on ties
__device__ __forceinline__ void top2upd(float s, int c, float& v1, int& i1, float& v2) {
    if (s > v1) { v2 = v1; v1 = s; i1 = c; }
    else if (s > v2) v2 = s;
}
// merge (ov1,oi1,ov2) into (v1,i1,v2), lower idx wins ties
__device__ __forceinline__ void top2merge(float ov1, int oi1, float ov2,
                                          float& v1, int& i1, float& v2) {
    float c2 = fmaxf(fmaxf(v2, ov2), fminf(v1, ov1));
    if (ov1 > v1 || (ov1 == v1 && oi1 < i1)) { v1 = ov1; i1 = oi1; }
    v2 = c2;
}

// ---------------- kernel 1: bias (exact fp32) + mem -> int8 ----------------
__global__ void k_prepB(const float* __restrict__ mem) {
    int row = blockIdx.x;
    const float* r = mem + (size_t)row * D_;
    int8_t* b = g_Bq + (size_t)row * D_;
    float s = 0.f;
    for (int i = threadIdx.x; i < D_; i += 128) {
        float v = r[i];
        int q = __float2int_rn(v * QB);
        q = max(-127, min(127, q));
        b[i] = (int8_t)q;
        s += v * v;
    }
#pragma unroll
    for (int o = 16; o; o >>= 1) s += __shfl_xor_sync(0xffffffffu, s, o);
    __shared__ float ws[4];
    if ((threadIdx.x & 31) == 0) ws[threadIdx.x >> 5] = s;
    __syncthreads();
    if (threadIdx.x == 0) g_bias[row] = -0.5f * (ws[0] + ws[1] + ws[2] + ws[3]);
}

// ---------------- kernel 2: im2col -> int8, layout [l][d] ----------------
__global__ void k_im2colA(const float* __restrict__ image) {
    const int l = blockIdx.x;                  // 0..LPAD-1
    const bool valid = l < L_;
    const int lh = l / LWW, lw = l - lh * LWW;
    int8_t* aq = g_Aq + (size_t)l * D_;
    for (int d = threadIdx.x; d < D_; d += 256) {
        float v = 0.f;
        if (valid) {
            int c = d >> 10, kh = (d >> 5) & 31, kw = d & 31;
            int y = lh + kh - PADP, x = lw + kw - PADP;
            if ((unsigned)y < HH && (unsigned)x < WW)
                v = image[(y * WW + x) * CC + c];
        }
        aq[d] = (int8_t)__float2int_rn(v * 127.0f);   // v in [0,1)
    }
}

// ---------------- kernel 3: int8 mma.sync GEMM -> scores + per-tile top2 ----------------
// CTA 128x128, 256 threads, warps 4(M)x2(N), warp tile 32x64 (R9 layout).
// TK=128 int8 per stage (4 k32 slices), 3 stages, 2 CTAs/SM.
// s8 m16n8k32 fragment byte-layout == bf16 m16n8k16 -> identical ldmatrix code.
__global__ __launch_bounds__(256, 2) void k_gemm() {
    extern __shared__ char smem[];
    const uint32_t sb = smem_u32(smem);
    const int tid = threadIdx.x, lane = tid & 31, wid = tid >> 5;
    const int wm = (wid & 3) * 32, wn = (wid >> 2) * 64;
    const int rowBase = blockIdx.x * TM, nBase = blockIdx.y * TNB;

    int acc[2][8][4];
#pragma unroll
    for (int mi = 0; mi < 2; ++mi)
#pragma unroll
        for (int nj = 0; nj < 8; ++nj)
#pragma unroll
            for (int q = 0; q < 4; ++q) acc[mi][nj][q] = 0;

    auto load_stage = [&](int kt) {
        const int slot = kt % 3;
        const uint32_t a0 = sb + slot * STG;
        const uint32_t b0 = a0 + ASTG;
        const int k0 = kt * TK;                // byte offset (1B/elem)
#pragma unroll
        for (int i = 0; i < 4; ++i) {          // A: 1024 chunks of 16B
            int idx = tid + i * 256;
            int r = idx >> 3, c = idx & 7;
            cp16(a0 + r * AROW + c * 16,
                 g_Aq + (size_t)(rowBase + r) * D_ + k0 + c * 16);
        }
#pragma unroll
        for (int i = 0; i < 4; ++i) {          // B: 1024 chunks of 16B
            int idx = tid + i * 256;
            int r = idx >> 3, c = idx & 7;
            cp16(b0 + r * AROW + c * 16,
                 g_Bq + (size_t)(nBase + r) * D_ + k0 + c * 16);
        }
    };

    load_stage(0); cp_commit();
    load_stage(1); cp_commit();

    for (int kt = 0; kt < NKT; ++kt) {
        cp_wait<1>();
        __syncthreads();
        if (kt + 2 < NKT) load_stage(kt + 2);
        cp_commit();

        const uint32_t a0 = sb + (kt % 3) * STG;
        const uint32_t b0 = a0 + ASTG;
#pragma unroll
        for (int ks = 0; ks < 4; ++ks) {       // four k32 slices (32B each)
            uint32_t af[2][4];
#pragma unroll
            for (int mi = 0; mi < 2; ++mi) {
                uint32_t addr = a0 + (wm + mi * 16 + (lane & 15)) * AROW
                              + ks * 32 + ((lane >> 4) & 1) * 16;
                asm volatile("ldmatrix.sync.aligned.m8n8.x4.shared.b16 {%0,%1,%2,%3}, [%4];"
                    : "=r"(af[mi][0]), "=r"(af[mi][1]), "=r"(af[mi][2]), "=r"(af[mi][3])
                    : "r"(addr));
            }
            // B n-major (k contiguous): non-trans ldmatrix, pair {r0,r2}/{r1,r3}
            uint32_t bfr[8][2];
#pragma unroll
            for (int ni = 0; ni < 4; ++ni) {
                uint32_t r0, r1, r2, r3;
                uint32_t addr = b0 + (wn + ni * 16 + (lane & 15)) * AROW
                              + ks * 32 + ((lane >> 4) & 1) * 16;
                asm volatile("ldmatrix.sync.aligned.m8n8.x4.shared.b16 {%0,%1,%2,%3}, [%4];"
                    : "=r"(r0), "=r"(r1), "=r"(r2), "=r"(r3) : "r"(addr));
                bfr[ni * 2][0]     = r0; bfr[ni * 2][1]     = r2;
                bfr[ni * 2 + 1][0] = r1; bfr[ni * 2 + 1][1] = r3;
            }
#pragma unroll
            for (int mi = 0; mi < 2; ++mi)
#pragma unroll
                for (int nj = 0; nj < 8; ++nj) {
                    asm volatile(
                        "mma.sync.aligned.m16n8k32.row.col.s32.s8.s8.s32 "
                        "{%0,%1,%2,%3}, {%4,%5,%6,%7}, {%8,%9}, {%0,%1,%2,%3};"
                        : "+r"(acc[mi][nj][0]), "+r"(acc[mi][nj][1]),
                          "+r"(acc[mi][nj][2]), "+r"(acc[mi][nj][3])
                        : "r"(af[mi][0]), "r"(af[mi][1]), "r"(af[mi][2]), "r"(af[mi][3]),
                          "r"(bfr[nj][0]), "r"(bfr[nj][1]));
                }
        }
    }

    // ---- epilogue: dequant + bias -> scores, fused per-row tile top1/top2 ----
    __syncthreads();                           // staging smem free; reuse it
    float* sv1 = (float*)smem;                 // [2 nwarp][128 rows]
    int*   si1 = (int*)(smem + 1024);
    float* sv2 = (float*)(smem + 2048);
    const int nw = wid >> 2;

#pragma unroll
    for (int mi = 0; mi < 2; ++mi) {
        const int rloc = wm + mi * 16 + (lane >> 2);   // local row (a); row b = +8
        float v1a = -3.4e38f, v2a = -3.4e38f; int i1a = 0;
        float v1b = -3.4e38f, v2b = -3.4e38f; int i1b = 0;
        const int row0 = rowBase + rloc;
#pragma unroll
        for (int nj = 0; nj < 8; ++nj) {
            const int col = nBase + wn + nj * 8 + (lane & 3) * 2;
            float2 bv = *(const float2*)(g_bias + col);
            float s0 = (float)acc[mi][nj][0] * RECON + bv.x;
            float s1 = (float)acc[mi][nj][1] * RECON + bv.y;
            float s2 = (float)acc[mi][nj][2] * RECON + bv.x;
            float s3 = (float)acc[mi][nj][3] * RECON + bv.y;
            *(float2*)(g_scores + (size_t)row0 * NMEM + col) = make_float2(s0, s1);
            *(float2*)(g_scores + (size_t)(row0 + 8) * NMEM + col) = make_float2(s2, s3);
            top2upd(s0, col, v1a, i1a, v2a);  top2upd(s1, col + 1, v1a, i1a, v2a);
            top2upd(s2, col, v1b, i1b, v2b);  top2upd(s3, col + 1, v1b, i1b, v2b);
        }
#pragma unroll
        for (int o = 1; o <= 2; o <<= 1) {
            float ov1 = __shfl_xor_sync(0xffffffffu, v1a, o);
            int   oi1 = __shfl_xor_sync(0xffffffffu, i1a, o);
            float ov2 = __shfl_xor_sync(0xffffffffu, v2a, o);
            top2merge(ov1, oi1, ov2, v1a, i1a, v2a);
            ov1 = __shfl_xor_sync(0xffffffffu, v1b, o);
            oi1 = __shfl_xor_sync(0xffffffffu, i1b, o);
            ov2 = __shfl_xor_sync(0xffffffffu, v2b, o);
            top2merge(ov1, oi1, ov2, v1b, i1b, v2b);
        }
        if ((lane & 3) == 0) {
            sv1[nw * 128 + rloc] = v1a; si1[nw * 128 + rloc] = i1a; sv2[nw * 128 + rloc] = v2a;
            sv1[nw * 128 + rloc + 8] = v1b; si1[nw * 128 + rloc + 8] = i1b; sv2[nw * 128 + rloc + 8] = v2b;
        }
    }
    __syncthreads();
    if (tid < 128) {
        float v1 = sv1[tid]; int i1 = si1[tid]; float v2 = sv2[tid];
        top2merge(sv1[128 + tid], si1[128 + tid], sv2[128 + tid], v1, i1, v2);
        const size_t gi = (size_t)(rowBase + tid) * NT + blockIdx.y;
        g_t1v[gi] = v1; g_t1i[gi] = i1; g_t2v[gi] = v2;
    }
}

// ---------------- kernel 4: reduce tile records, decide or collect candidates ----------------
__global__ void k_select(const int* __restrict__ mapping) {
    if (blockIdx.x == 0 && threadIdx.x == 0) g_maxkey = 0u;   // reset for fold
    const int l = (blockIdx.x * blockDim.x + threadIdx.x) >> 5;
    const int lane = threadIdx.x & 31;
    if (l >= L_) return;

    // one lane per N-tile (32 tiles), coalesced
    float m1 = g_t1v[(size_t)l * NT + lane];
    int   i1 = g_t1i[(size_t)l * NT + lane];
    float m2 = g_t2v[(size_t)l * NT + lane];
#pragma unroll
    for (int off = 16; off; off >>= 1) {
        float om1 = __shfl_xor_sync(0xffffffffu, m1, off);
        float om2 = __shfl_xor_sync(0xffffffffu, m2, off);
        int   oi1 = __shfl_xor_sync(0xffffffffu, i1, off);
        top2merge(om1, oi1, om2, m1, i1, m2);
    }

    if (m1 - m2 > MARGIN) {
        if (lane == 0) { g_pid[l] = mapping[i1]; g_candcnt[l] = 1; }
        return;
    }
    // ambiguous: collect candidates within MARGIN from the stored score row
    const float* row = g_scores + (size_t)l * NMEM;
    const float thr = m1 - MARGIN;
    int base = 0;
    for (int n0 = 0; n0 < NMEM; n0 += 32) {
        float v = row[n0 + lane];
        bool p = v >= thr;
        unsigned mask = __ballot_sync(0xffffffffu, p);
        if (p) {
            int pos = base + __popc(mask & ((1u << lane) - 1u));
            if (pos < CMAX) g_cand[(size_t)l * CMAX + pos] = n0 + lane;
        }
        base += __popc(mask);
    }
    if (lane == 0) g_candcnt[l] = base;   // may exceed CMAX -> full rescan
}

// ---------------- kernel 5: exact fp32 rescue for ambiguous patches ----------------
__global__ void k_rescore(const float* __restrict__ image,
                          const float* __restrict__ mem,
                          const int* __restrict__ mapping) {
    const int l = blockIdx.x;
    const int cnt = g_candcnt[l];
    if (cnt <= 1) return;

    __shared__ float sp[D_];     // 12 KB exact patch
    __shared__ float red[4];
    const int lh = l / LWW, lw = l - lh * LWW;
    for (int d = threadIdx.x; d < D_; d += 128) {
        int c = d >> 10, kh = (d >> 5) & 31, kw = d & 31;
        int y = lh + kh - PADP, x = lw + kw - PADP;
        float v = 0.f;
        if ((unsigned)y < HH && (unsigned)x < WW)
            v = image[(y * WW + x) * CC + c];
        sp[d] = v;
    }
    __syncthreads();

    const bool full = cnt > CMAX;
    const int num = full ? NMEM : cnt;
    float best = -3.4e38f;
    int bestn = 0;
    for (int c = 0; c < num; ++c) {
        const int n = full ? c : g_cand[(size_t)l * CMAX + c];
        const float* mrow = mem + (size_t)n * D_;
        float s = 0.f;
        for (int k = threadIdx.x; k < D_; k += 128) s = fmaf(sp[k], mrow[k], s);
#pragma unroll
        for (int o = 16; o; o >>= 1) s += __shfl_xor_sync(0xffffffffu, s, o);
        if ((threadIdx.x & 31) == 0) red[threadIdx.x >> 5] = s;
        __syncthreads();
        if (threadIdx.x == 0) {
            float tot = red[0] + red[1] + red[2] + red[3] + g_bias[n];
            if (tot > best) { best = tot; bestn = n; }   // ascending n -> first max wins
        }
        __syncthreads();
    }
    if (threadIdx.x == 0) g_pid[l] = mapping[bestn];
}

// ---------------- kernel 6: fold (gather) + global max ----------------
__global__ void k_fold(const float* __restrict__ mem2) {
    __shared__ int spid[32 * LWW];
    const int h = blockIdx.x;
    const int c = blockIdx.y;
    const int w = threadIdx.x;               // 0..127

    const int lh0 = max(0, h - (KHH - 1 - PADP));
    const int lh1 = min(LHH - 1, h + PADP);
    const int nrows = lh1 - lh0 + 1;
    for (int idx = threadIdx.x; idx < nrows * LWW; idx += 128)
        spid[idx] = g_pid[(lh0 + idx / LWW) * LWW + idx % LWW];
    __syncthreads();

    float s = 0.f;
#pragma unroll 1
    for (int kh = 0; kh < KHH; ++kh) {
        int lh = h + PADP - kh;
        if (lh < lh0 || lh > lh1) continue;
        const int base = (lh - lh0) * LWW;
        const int rowoff = c * 1024 + kh * 32;
#pragma unroll
        for (int kw = 0; kw < KWW; ++kw) {
            int lw = w + PADP - kw;
            if ((unsigned)lw < LWW) {
                int pid = spid[base + lw];
                s += __ldg(&mem2[(size_t)pid * D_ + rowoff + kw]);
            }
        }
    }
    g_facc[(c * HH + h) * WW + w] = s;

    float m = s;
#pragma unroll
    for (int o = 16; o; o >>= 1) m = fmaxf(m, __shfl_xor_sync(0xffffffffu, m, o));
    __shared__ float wm[4];
    if ((threadIdx.x & 31) == 0) wm[threadIdx.x >> 5] = m;
    __syncthreads();
    if (threadIdx.x == 0) {
        m = fmaxf(fmaxf(wm[0], wm[1]), fmaxf(wm[2], wm[3]));
        unsigned b = __float_as_uint(m);
        unsigned key = (b & 0x80000000u) ? ~b : (b | 0x80000000u);
        atomicMax(&g_maxkey, key);
    }
}

// ---------------- kernel 7: normalize + transpose to (H,W,C) ----------------
__global__ void k_norm(float* __restrict__ out) {
    int i = blockIdx.x * 256 + threadIdx.x;
    if (i >= HH * WW * CC) return;
    unsigned key = g_maxkey;
    unsigned b = (key & 0x80000000u) ? (key & 0x7fffffffu) : ~key;
    float mx = __uint_as_float(b);
    int c = i % CC;
    int w = (i / CC) % WW;
    int h = i / (CC * WW);
    out[i] = g_facc[(c * HH + h) * WW + w] / mx;
}

// ---------------- launcher ----------------
extern "C" void kernel_launch(void* const* d_in, const int* in_sizes, int n_in,
                              void* d_out, int out_size) {
    const float* image   = (const float*)d_in[0];
    const float* mem     = (const float*)d_in[1];
    const float* mem2    = (const float*)d_in[2];
    const int*   mapping = (const int*)d_in[3];
    float* out = (float*)d_out;

    cudaFuncSetAttribute(k_gemm, cudaFuncAttributeMaxDynamicSharedMemorySize, SMEM_GEMM);

    k_prepB<<<NMEM, 128>>>(mem);
    k_im2colA<<<LPAD, 256>>>(image);
    k_gemm<<<dim3(LPAD / TM, NMEM / TNB), 256, SMEM_GEMM>>>();
    k_select<<<(L_ + 7) / 8, 256>>>(mapping);
    k_rescore<<<L_, 128>>>(image, mem, mapping);
    k_fold<<<dim3(HH, CC), 128>>>(mem2);
    k_norm<<<(HH * WW * CC + 255) / 256, 256>>>(out);
}

// round 13
// speedup vs baseline: 2.0349x; 2.0349x over previous
#include <cuda_runtime.h>
#include <cuda_bf16.h>
#include <cstdint>

// ---------------- problem constants ----------------
#define L_      13689           // LH*LW
#define LPAD    13696           // 107 * 128
#define D_      3072            // C*KH*KW
#define NMEM    4096
#define HH      128
#define WW      128
#define CC      3
#define KHH     32
#define KWW     32
#define PADP    10
#define LHH     117
#define LWW     117

// ---------------- GEMM tiling (mma.sync bf16, m16n8k16) ----------------
#define TM      128              // CTA M
#define TNB     128              // CTA N
#define NT      (NMEM / TNB)     // 32 N-tiles
#define TK      64               // K per stage (4 k16 slices)
#define NKT     (D_ / TK)        // 48
#define AROW    144              // bytes per smem row: 64 bf16 (128B) + 16B pad
#define ASTG    (TM * AROW)      // 18432
#define BSTG    (TNB * AROW)     // 18432
#define STG     (ASTG + BSTG)    // 36864
#define SMEM_GEMM (3 * STG)      // 110592 (3 stages) -> 2 CTAs/SM

#define MARGIN  2.0f
#define CMAX    16

typedef unsigned long long ull;

// ---------------- static device scratch ----------------
__device__ __align__(16) __nv_bfloat16 g_Abf [(size_t)LPAD * D_];   // 84 MB
__device__ __align__(16) __nv_bfloat16 g_Bbf [(size_t)NMEM * D_];   // 25 MB
__device__ __align__(16) float         g_bias[NMEM];                // -0.5*||mem_n||^2 exact
__device__ __align__(16) float         g_scores[(size_t)LPAD * NMEM]; // 224 MB
__device__ __align__(16) float4 g_top[(size_t)LPAD * NT];            // (v1, v2, idx-bits, -)
__device__ int   g_cand[(size_t)L_ * CMAX];
__device__ int   g_candcnt[L_];
__device__ int   g_pid[L_];
__device__ float g_facc[CC * HH * WW];
__device__ unsigned int g_maxkey;

// ---------------- helpers ----------------
__device__ __forceinline__ uint32_t smem_u32(const void* p) {
    uint32_t a;
    asm("{ .reg .u64 t; cvta.to.shared.u64 t, %1; cvt.u32.u64 %0, t; }" : "=r"(a) : "l"(p));
    return a;
}
__device__ __forceinline__ void cp16(uint32_t smem_dst, const void* gsrc) {
    asm volatile("cp.async.cg.shared.global [%0], [%1], 16;" :: "r"(smem_dst), "l"(gsrc));
}
__device__ __forceinline__ void cp_commit() { asm volatile("cp.async.commit_group;"); }
template <int N> __device__ __forceinline__ void cp_wait() {
    asm volatile("cp.async.wait_group %0;" :: "n"(N));
}
// top-2 update; strict > keeps earliest (lowest n) on ties
__device__ __forceinline__ void top2upd(float s, int c, float& v1, int& i1, float& v2) {
    if (s > v1) { v2 = v1; v1 = s; i1 = c; }
    else if (s > v2) v2 = s;
}
// merge (ov1,oi1,ov2) into (v1,i1,v2), lower idx wins ties
__device__ __forceinline__ void top2merge(float ov1, int oi1, float ov2,
                                          float& v1, int& i1, float& v2) {
    float c2 = fmaxf(fmaxf(v2, ov2), fminf(v1, ov1));
    if (ov1 > v1 || (ov1 == v1 && oi1 < i1)) { v1 = ov1; i1 = oi1; }
    v2 = c2;
}

// ---------------- kernel 1: bias (exact fp32) + mem -> bf16 ----------------
__global__ void k_prepB(const float* __restrict__ mem) {
    int row = blockIdx.x;
    const float* r = mem + (size_t)row * D_;
    __nv_bfloat16* b = g_Bbf + (size_t)row * D_;
    float s = 0.f;
    for (int i = threadIdx.x; i < D_; i += 128) {
        float v = r[i];
        b[i] = __float2bfloat16(v);
        s += v * v;
    }
#pragma unroll
    for (int o = 16; o; o >>= 1) s += __shfl_xor_sync(0xffffffffu, s, o);
    __shared__ float ws[4];
    if ((threadIdx.x & 31) == 0) ws[threadIdx.x >> 5] = s;
    __syncthreads();
    if (threadIdx.x == 0) g_bias[row] = -0.5f * (ws[0] + ws[1] + ws[2] + ws[3]);
}

// ---------------- kernel 2: im2col -> bf16, layout [l][d] ----------------
__global__ void k_im2colA(const float* __restrict__ image) {
    const int l = blockIdx.x;                  // 0..LPAD-1
    const bool valid = l < L_;
    const int lh = l / LWW, lw = l - lh * LWW;
    __nv_bfloat16* abf = g_Abf + (size_t)l * D_;
    for (int d = threadIdx.x; d < D_; d += 256) {
        float v = 0.f;
        if (valid) {
            int c = d >> 10, kh = (d >> 5) & 31, kw = d & 31;
            int y = lh + kh - PADP, x = lw + kw - PADP;
            if ((unsigned)y < HH && (unsigned)x < WW)
                v = image[(y * WW + x) * CC + c];
        }
        abf[d] = __float2bfloat16(v);
    }
}

// ---------------- kernel 3: bf16 mma.sync GEMM -> scores + per-tile top2 ----------------
// CTA 128x128, 256 threads, warps 4(M)x2(N), warp tile 32x64. TK=64, 3 stages, 2 CTAs/SM.
// Grid: x = N-tile (fast), y = M-tile -> consecutive CTAs share the A band (L2 reuse).
__global__ __launch_bounds__(256, 2) void k_gemm() {
    extern __shared__ char smem[];
    const uint32_t sb = smem_u32(smem);
    const int tid = threadIdx.x, lane = tid & 31, wid = tid >> 5;
    const int wm = (wid & 3) * 32, wn = (wid >> 2) * 64;
    const int rowBase = blockIdx.y * TM, nBase = blockIdx.x * TNB;

    float acc[2][8][4];
#pragma unroll
    for (int mi = 0; mi < 2; ++mi)
#pragma unroll
        for (int nj = 0; nj < 8; ++nj)
#pragma unroll
            for (int q = 0; q < 4; ++q) acc[mi][nj][q] = 0.f;

    auto load_stage = [&](int kt) {
        const int slot = kt % 3;
        const uint32_t a0 = sb + slot * STG;
        const uint32_t b0 = a0 + ASTG;
        const int k0 = kt * TK;
#pragma unroll
        for (int i = 0; i < 4; ++i) {
            int idx = tid + i * 256;
            int r = idx >> 3, c = idx & 7;
            cp16(a0 + r * AROW + c * 16,
                 (const char*)g_Abf + ((size_t)(rowBase + r) * D_ + k0) * 2 + c * 16);
        }
#pragma unroll
        for (int i = 0; i < 4; ++i) {
            int idx = tid + i * 256;
            int r = idx >> 3, c = idx & 7;
            cp16(b0 + r * AROW + c * 16,
                 (const char*)g_Bbf + ((size_t)(nBase + r) * D_ + k0) * 2 + c * 16);
        }
    };

    load_stage(0); cp_commit();
    load_stage(1); cp_commit();

    for (int kt = 0; kt < NKT; ++kt) {
        cp_wait<1>();
        __syncthreads();
        if (kt + 2 < NKT) load_stage(kt + 2);
        cp_commit();

        const uint32_t a0 = sb + (kt % 3) * STG;
        const uint32_t b0 = a0 + ASTG;
#pragma unroll
        for (int kh = 0; kh < 4; ++kh) {
            uint32_t af[2][4];
#pragma unroll
            for (int mi = 0; mi < 2; ++mi) {
                uint32_t addr = a0 + (wm + mi * 16 + (lane & 15)) * AROW
                              + kh * 32 + ((lane >> 4) & 1) * 16;
                asm volatile("ldmatrix.sync.aligned.m8n8.x4.shared.b16 {%0,%1,%2,%3}, [%4];"
                    : "=r"(af[mi][0]), "=r"(af[mi][1]), "=r"(af[mi][2]), "=r"(af[mi][3])
                    : "r"(addr));
            }
            // B n-major (k contiguous): non-trans ldmatrix, pair {r0,r2}/{r1,r3}
            uint32_t bfr[8][2];
#pragma unroll
            for (int ni = 0; ni < 4; ++ni) {
                uint32_t r0, r1, r2, r3;
                uint32_t addr = b0 + (wn + ni * 16 + (lane & 15)) * AROW
                              + kh * 32 + ((lane >> 4) & 1) * 16;
                asm volatile("ldmatrix.sync.aligned.m8n8.x4.shared.b16 {%0,%1,%2,%3}, [%4];"
                    : "=r"(r0), "=r"(r1), "=r"(r2), "=r"(r3) : "r"(addr));
                bfr[ni * 2][0]     = r0; bfr[ni * 2][1]     = r2;
                bfr[ni * 2 + 1][0] = r1; bfr[ni * 2 + 1][1] = r3;
            }
#pragma unroll
            for (int mi = 0; mi < 2; ++mi)
#pragma unroll
                for (int nj = 0; nj < 8; ++nj) {
                    asm volatile(
                        "mma.sync.aligned.m16n8k16.row.col.f32.bf16.bf16.f32 "
                        "{%0,%1,%2,%3}, {%4,%5,%6,%7}, {%8,%9}, {%0,%1,%2,%3};"
                        : "+f"(acc[mi][nj][0]), "+f"(acc[mi][nj][1]),
                          "+f"(acc[mi][nj][2]), "+f"(acc[mi][nj][3])
                        : "r"(af[mi][0]), "r"(af[mi][1]), "r"(af[mi][2]), "r"(af[mi][3]),
                          "r"(bfr[nj][0]), "r"(bfr[nj][1]));
                }
        }
    }

    // ---- epilogue: scores + per-row tile top1/top2 ----
    __syncthreads();                           // staging smem free; reuse it
    float* sv1 = (float*)smem;                 // [2 nwarp][128 rows]
    int*   si1 = (int*)(smem + 1024);
    float* sv2 = (float*)(smem + 2048);
    const int nw = wid >> 2;

#pragma unroll
    for (int mi = 0; mi < 2; ++mi) {
        const int rloc = wm + mi * 16 + (lane >> 2);   // local row (a); row b = +8
        float v1a = -3.4e38f, v2a = -3.4e38f; int i1a = 0;
        float v1b = -3.4e38f, v2b = -3.4e38f; int i1b = 0;
        const int row0 = rowBase + rloc;
#pragma unroll
        for (int nj = 0; nj < 8; ++nj) {
            const int col = nBase + wn + nj * 8 + (lane & 3) * 2;
            float2 bv = *(const float2*)(g_bias + col);
            float s0 = acc[mi][nj][0] + bv.x, s1 = acc[mi][nj][1] + bv.y;
            float s2 = acc[mi][nj][2] + bv.x, s3 = acc[mi][nj][3] + bv.y;
            *(float2*)(g_scores + (size_t)row0 * NMEM + col) = make_float2(s0, s1);
            *(float2*)(g_scores + (size_t)(row0 + 8) * NMEM + col) = make_float2(s2, s3);
            top2upd(s0, col, v1a, i1a, v2a);  top2upd(s1, col + 1, v1a, i1a, v2a);
            top2upd(s2, col, v1b, i1b, v2b);  top2upd(s3, col + 1, v1b, i1b, v2b);
        }
#pragma unroll
        for (int o = 1; o <= 2; o <<= 1) {
            float ov1 = __shfl_xor_sync(0xffffffffu, v1a, o);
            int   oi1 = __shfl_xor_sync(0xffffffffu, i1a, o);
            float ov2 = __shfl_xor_sync(0xffffffffu, v2a, o);
            top2merge(ov1, oi1, ov2, v1a, i1a, v2a);
            ov1 = __shfl_xor_sync(0xffffffffu, v1b, o);
            oi1 = __shfl_xor_sync(0xffffffffu, i1b, o);
            ov2 = __shfl_xor_sync(0xffffffffu, v2b, o);
            top2merge(ov1, oi1, ov2, v1b, i1b, v2b);
        }
        if ((lane & 3) == 0) {
            sv1[nw * 128 + rloc] = v1a; si1[nw * 128 + rloc] = i1a; sv2[nw * 128 + rloc] = v2a;
            sv1[nw * 128 + rloc + 8] = v1b; si1[nw * 128 + rloc + 8] = i1b; sv2[nw * 128 + rloc + 8] = v2b;
        }
    }
    __syncthreads();
    if (tid < 128) {
        float v1 = sv1[tid]; int i1 = si1[tid]; float v2 = sv2[tid];
        top2merge(sv1[128 + tid], si1[128 + tid], sv2[128 + tid], v1, i1, v2);
        g_top[(size_t)(rowBase + tid) * NT + blockIdx.x] =
            make_float4(v1, v2, __int_as_float(i1), 0.f);
    }
}

// ---------------- kernel 4: reduce tile records, decide or collect candidates ----------------
__global__ void k_select(const int* __restrict__ mapping) {
    if (blockIdx.x == 0 && threadIdx.x == 0) g_maxkey = 0u;   // reset for fold
    const int l = (blockIdx.x * blockDim.x + threadIdx.x) >> 5;
    const int lane = threadIdx.x & 31;
    if (l >= L_) return;

    // one lane per N-tile (32 tiles), single 16B load
    float4 rec = g_top[(size_t)l * NT + lane];
    float m1 = rec.x, m2 = rec.y;
    int   i1 = __float_as_int(rec.z);
#pragma unroll
    for (int off = 16; off; off >>= 1) {
        float om1 = __shfl_xor_sync(0xffffffffu, m1, off);
        float om2 = __shfl_xor_sync(0xffffffffu, m2, off);
        int   oi1 = __shfl_xor_sync(0xffffffffu, i1, off);
        top2merge(om1, oi1, om2, m1, i1, m2);
    }

    if (m1 - m2 > MARGIN) {
        if (lane == 0) { g_pid[l] = mapping[i1]; g_candcnt[l] = 1; }
        return;
    }
    // ambiguous: collect candidates within MARGIN from the stored score row
    const float* row = g_scores + (size_t)l * NMEM;
    const float thr = m1 - MARGIN;
    int base = 0;
    for (int n0 = 0; n0 < NMEM; n0 += 32) {
        float v = row[n0 + lane];
        bool p = v >= thr;
        unsigned mask = __ballot_sync(0xffffffffu, p);
        if (p) {
            int pos = base + __popc(mask & ((1u << lane) - 1u));
            if (pos < CMAX) g_cand[(size_t)l * CMAX + pos] = n0 + lane;
        }
        base += __popc(mask);
    }
    if (lane == 0) g_candcnt[l] = base;   // may exceed CMAX -> full rescan
}

// ---------------- kernel 5: exact fp32 rescue for ambiguous patches ----------------
__global__ void k_rescore(const float* __restrict__ image,
                          const float* __restrict__ mem,
                          const int* __restrict__ mapping) {
    const int l = blockIdx.x;
    const int cnt = g_candcnt[l];
    if (cnt <= 1) return;

    __shared__ float sp[D_];     // 12 KB exact patch
    __shared__ float red[4];
    const int lh = l / LWW, lw = l - lh * LWW;
    for (int d = threadIdx.x; d < D_; d += 128) {
        int c = d >> 10, kh = (d >> 5) & 31, kw = d & 31;
        int y = lh + kh - PADP, x = lw + kw - PADP;
        float v = 0.f;
        if ((unsigned)y < HH && (unsigned)x < WW)
            v = image[(y * WW + x) * CC + c];
        sp[d] = v;
    }
    __syncthreads();

    const bool full = cnt > CMAX;
    const int num = full ? NMEM : cnt;
    float best = -3.4e38f;
    int bestn = 0;
    for (int c = 0; c < num; ++c) {
        const int n = full ? c : g_cand[(size_t)l * CMAX + c];
        const float* mrow = mem + (size_t)n * D_;
        float s = 0.f;
        for (int k = threadIdx.x; k < D_; k += 128) s = fmaf(sp[k], mrow[k], s);
#pragma unroll
        for (int o = 16; o; o >>= 1) s += __shfl_xor_sync(0xffffffffu, s, o);
        if ((threadIdx.x & 31) == 0) red[threadIdx.x >> 5] = s;
        __syncthreads();
        if (threadIdx.x == 0) {
            float tot = red[0] + red[1] + red[2] + red[3] + g_bias[n];
            if (tot > best) { best = tot; bestn = n; }   // ascending n -> first max wins
        }
        __syncthreads();
    }
    if (threadIdx.x == 0) g_pid[l] = mapping[bestn];
}

// ---------------- kernel 6: fold (gather) + global max ----------------
__global__ void k_fold(const float* __restrict__ mem2) {
    __shared__ int spid[32 * LWW];
    const int h = blockIdx.x;
    const int c = blockIdx.y;
    const int w = threadIdx.x;               // 0..127

    const int lh0 = max(0, h - (KHH - 1 - PADP));
    const int lh1 = min(LHH - 1, h + PADP);
    const int nrows = lh1 - lh0 + 1;
    for (int idx = threadIdx.x; idx < nrows * LWW; idx += 128)
        spid[idx] = g_pid[(lh0 + idx / LWW) * LWW + idx % LWW];
    __syncthreads();

    float s = 0.f;
#pragma unroll 1
    for (int kh = 0; kh < KHH; ++kh) {
        int lh = h + PADP - kh;
        if (lh < lh0 || lh > lh1) continue;
        const int base = (lh - lh0) * LWW;
        const int rowoff = c * 1024 + kh * 32;
#pragma unroll
        for (int kw = 0; kw < KWW; ++kw) {
            int lw = w + PADP - kw;
            if ((unsigned)lw < LWW) {
                int pid = spid[base + lw];
                s += __ldg(&mem2[(size_t)pid * D_ + rowoff + kw]);
            }
        }
    }
    g_facc[(c * HH + h) * WW + w] = s;

    float m = s;
#pragma unroll
    for (int o = 16; o; o >>= 1) m = fmaxf(m, __shfl_xor_sync(0xffffffffu, m, o));
    __shared__ float wm[4];
    if ((threadIdx.x & 31) == 0) wm[threadIdx.x >> 5] = m;
    __syncthreads();
    if (threadIdx.x == 0) {
        m = fmaxf(fmaxf(wm[0], wm[1]), fmaxf(wm[2], wm[3]));
        unsigned b = __float_as_uint(m);
        unsigned key = (b & 0x80000000u) ? ~b : (b | 0x80000000u);
        atomicMax(&g_maxkey, key);
    }
}

// ---------------- kernel 7: normalize + transpose to (H,W,C) ----------------
__global__ void k_norm(float* __restrict__ out) {
    int i = blockIdx.x * 256 + threadIdx.x;
    if (i >= HH * WW * CC) return;
    unsigned key = g_maxkey;
    unsigned b = (key & 0x80000000u) ? (key & 0x7fffffffu) : ~key;
    float mx = __uint_as_float(b);
    int c = i % CC;
    int w = (i / CC) % WW;
    int h = i / (CC * WW);
    out[i] = g_facc[(c * HH + h) * WW + w] / mx;
}

// ---------------- launcher ----------------
extern "C" void kernel_launch(void* const* d_in, const int* in_sizes, int n_in,
                              void* d_out, int out_size) {
    const float* image   = (const float*)d_in[0];
    const float* mem     = (const float*)d_in[1];
    const float* mem2    = (const float*)d_in[2];
    const int*   mapping = (const int*)d_in[3];
    float* out = (float*)d_out;

    cudaFuncSetAttribute(k_gemm, cudaFuncAttributeMaxDynamicSharedMemorySize, SMEM_GEMM);

    k_prepB<<<NMEM, 128>>>(mem);
    k_im2colA<<<LPAD, 256>>>(image);
    k_gemm<<<dim3(NMEM / TNB, LPAD / TM), 256, SMEM_GEMM>>>();
    k_select<<<(L_ + 7) / 8, 256>>>(mapping);
    k_rescore<<<L_, 128>>>(image, mem, mapping);
    k_fold<<<dim3(HH, CC), 128>>>(mem2);
    k_norm<<<(HH * WW * CC + 255) / 256, 256>>>(out);
}

// round 16
// speedup vs baseline: 2.3617x; 1.1606x over previous
#include <cuda_runtime.h>
#include <cuda_bf16.h>
#include <cstdint>

// ---------------- problem constants ----------------
#define L_      13689           // LH*LW
#define LPAD    13696           // 107 * 128
#define D_      3072            // C*KH*KW
#define NMEM    4096
#define HH      128
#define WW      128
#define CC      3
#define KHH     32
#define KWW     32
#define PADP    10
#define LHH     117
#define LWW     117

// ---------------- GEMM tiling (mma.sync bf16, m16n8k16) ----------------
#define TM      128              // CTA M
#define TNB     128              // CTA N
#define NT      (NMEM / TNB)     // 32 N-tiles
#define TK      64               // K per stage (4 k16 slices)
#define NKT     (D_ / TK)        // 48
#define AROW    144              // bytes per smem row: 64 bf16 (128B) + 16B pad
#define ASTG    (TM * AROW)      // 18432
#define BSTG    (TNB * AROW)     // 18432
#define STG     (ASTG + BSTG)    // 36864
#define SMEM_GEMM (3 * STG)      // 110592 (3 stages) -> 2 CTAs/SM

#define MARGIN  2.0f             // fp32 score storage: only bf16 gemm error
#define CMAX    16

typedef unsigned long long ull;

// ---------------- static device scratch ----------------
__device__ __align__(16) __nv_bfloat16 g_Abf [(size_t)LPAD * D_];   // 84 MB
__device__ __align__(16) __nv_bfloat16 g_Bbf [(size_t)NMEM * D_];   // 25 MB
__device__ __align__(16) float         g_bias[NMEM];                // -0.5*||mem_n||^2 exact
__device__ __align__(16) float         g_scores[(size_t)LPAD * NMEM]; // 224 MB fp32
__device__ __align__(16) float4 g_top[(size_t)LPAD * NT];            // (v1, v2, idx-bits, -)
__device__ int   g_cand[(size_t)L_ * CMAX];
__device__ int   g_candcnt[L_];
__device__ int   g_pid[L_];
__device__ float g_facc[CC * HH * WW];
__device__ unsigned int g_maxkey;

// ---------------- helpers ----------------
__device__ __forceinline__ uint32_t smem_u32(const void* p) {
    uint32_t a;
    asm("{ .reg .u64 t; cvta.to.shared.u64 t, %1; cvt.u32.u64 %0, t; }" : "=r"(a) : "l"(p));
    return a;
}
__device__ __forceinline__ void cp16(uint32_t smem_dst, const void* gsrc) {
    asm volatile("cp.async.cg.shared.global [%0], [%1], 16;" :: "r"(smem_dst), "l"(gsrc));
}
__device__ __forceinline__ void cp_commit() { asm volatile("cp.async.commit_group;"); }
template <int N> __device__ __forceinline__ void cp_wait() {
    asm volatile("cp.async.wait_group %0;" :: "n"(N));
}
// top-2 update; strict > keeps earliest (lowest n) on ties
__device__ __forceinline__ void top2upd(float s, int c, float& v1, int& i1, float& v2) {
    if (s > v1) { v2 = v1; v1 = s; i1 = c; }
    else if (s > v2) v2 = s;
}
// merge (ov1,oi1,ov2) into (v1,i1,v2), lower idx wins ties
__device__ __forceinline__ void top2merge(float ov1, int oi1, float ov2,
                                          float& v1, int& i1, float& v2) {
    float c2 = fmaxf(fmaxf(v2, ov2), fminf(v1, ov1));
    if (ov1 > v1 || (ov1 == v1 && oi1 < i1)) { v1 = ov1; i1 = oi1; }
    v2 = c2;
}

// ---------------- kernel 1: bias (exact fp32) + mem -> bf16 ----------------
__global__ void k_prepB(const float* __restrict__ mem) {
    int row = blockIdx.x;
    const float* r = mem + (size_t)row * D_;
    __nv_bfloat16* b = g_Bbf + (size_t)row * D_;
    float s = 0.f;
    for (int i = threadIdx.x; i < D_; i += 128) {
        float v = r[i];
        b[i] = __float2bfloat16(v);
        s += v * v;
    }
#pragma unroll
    for (int o = 16; o; o >>= 1) s += __shfl_xor_sync(0xffffffffu, s, o);
    __shared__ float ws[4];
    if ((threadIdx.x & 31) == 0) ws[threadIdx.x >> 5] = s;
    __syncthreads();
    if (threadIdx.x == 0) g_bias[row] = -0.5f * (ws[0] + ws[1] + ws[2] + ws[3]);
}

// ---------------- kernel 2: im2col -> bf16, layout [l][d] ----------------
__global__ void k_im2colA(const float* __restrict__ image) {
    const int l = blockIdx.x;                  // 0..LPAD-1
    const bool valid = l < L_;
    const int lh = l / LWW, lw = l - lh * LWW;
    __nv_bfloat16* abf = g_Abf + (size_t)l * D_;
    for (int d = threadIdx.x; d < D_; d += 256) {
        float v = 0.f;
        if (valid) {
            int c = d >> 10, kh = (d >> 5) & 31, kw = d & 31;
            int y = lh + kh - PADP, x = lw + kw - PADP;
            if ((unsigned)y < HH && (unsigned)x < WW)
                v = image[(y * WW + x) * CC + c];
        }
        abf[d] = __float2bfloat16(v);
    }
}

// ---------------- kernel 3: bf16 mma.sync GEMM -> fp32 scores + per-tile top2 ----------------
// CTA 128x128, 256 threads, warps 4(M)x2(N), warp tile 32x64. TK=64, 3 stages, 2 CTAs/SM.
// Next-stage cp.async issued in quarters interleaved with the 4 kh slices (smooth crossbar).
__global__ __launch_bounds__(256, 2) void k_gemm() {
    extern __shared__ char smem[];
    const uint32_t sb = smem_u32(smem);
    const int tid = threadIdx.x, lane = tid & 31, wid = tid >> 5;
    const int wm = (wid & 3) * 32, wn = (wid >> 2) * 64;
    const int rowBase = blockIdx.y * TM, nBase = blockIdx.x * TNB;

    float acc[2][8][4];
#pragma unroll
    for (int mi = 0; mi < 2; ++mi)
#pragma unroll
        for (int nj = 0; nj < 8; ++nj)
#pragma unroll
            for (int q = 0; q < 4; ++q) acc[mi][nj][q] = 0.f;

    // one quarter (1 A chunk + 1 B chunk per thread) of a stage load
    auto load_q = [&](int kt, int q) {
        const int slot = kt % 3;
        const uint32_t a0 = sb + slot * STG;
        const uint32_t b0 = a0 + ASTG;
        const int k0 = kt * TK;
        int idx = tid + q * 256;
        int r = idx >> 3, c = idx & 7;
        cp16(a0 + r * AROW + c * 16,
             (const char*)g_Abf + ((size_t)(rowBase + r) * D_ + k0) * 2 + c * 16);
        cp16(b0 + r * AROW + c * 16,
             (const char*)g_Bbf + ((size_t)(nBase + r) * D_ + k0) * 2 + c * 16);
    };

#pragma unroll
    for (int q = 0; q < 4; ++q) load_q(0, q);
    cp_commit();
#pragma unroll
    for (int q = 0; q < 4; ++q) load_q(1, q);
    cp_commit();

    for (int kt = 0; kt < NKT; ++kt) {
        cp_wait<1>();
        __syncthreads();

        const uint32_t a0 = sb + (kt % 3) * STG;
        const uint32_t b0 = a0 + ASTG;
        const bool pf = (kt + 2 < NKT);
#pragma unroll
        for (int kh = 0; kh < 4; ++kh) {
            if (pf) load_q(kt + 2, kh);      // spread next-stage cp.async across slices
            uint32_t af[2][4];
#pragma unroll
            for (int mi = 0; mi < 2; ++mi) {
                uint32_t addr = a0 + (wm + mi * 16 + (lane & 15)) * AROW
                              + kh * 32 + ((lane >> 4) & 1) * 16;
                asm volatile("ldmatrix.sync.aligned.m8n8.x4.shared.b16 {%0,%1,%2,%3}, [%4];"
                    : "=r"(af[mi][0]), "=r"(af[mi][1]), "=r"(af[mi][2]), "=r"(af[mi][3])
                    : "r"(addr));
            }
            // B n-major (k contiguous): non-trans ldmatrix, pair {r0,r2}/{r1,r3}
            uint32_t bfr[8][2];
#pragma unroll
            for (int ni = 0; ni < 4; ++ni) {
                uint32_t r0, r1, r2, r3;
                uint32_t addr = b0 + (wn + ni * 16 + (lane & 15)) * AROW
                              + kh * 32 + ((lane >> 4) & 1) * 16;
                asm volatile("ldmatrix.sync.aligned.m8n8.x4.shared.b16 {%0,%1,%2,%3}, [%4];"
                    : "=r"(r0), "=r"(r1), "=r"(r2), "=r"(r3) : "r"(addr));
                bfr[ni * 2][0]     = r0; bfr[ni * 2][1]     = r2;
                bfr[ni * 2 + 1][0] = r1; bfr[ni * 2 + 1][1] = r3;
            }
#pragma unroll
            for (int mi = 0; mi < 2; ++mi)
#pragma unroll
                for (int nj = 0; nj < 8; ++nj) {
                    asm volatile(
                        "mma.sync.aligned.m16n8k16.row.col.f32.bf16.bf16.f32 "
                        "{%0,%1,%2,%3}, {%4,%5,%6,%7}, {%8,%9}, {%0,%1,%2,%3};"
                        : "+f"(acc[mi][nj][0]), "+f"(acc[mi][nj][1]),
                          "+f"(acc[mi][nj][2]), "+f"(acc[mi][nj][3])
                        : "r"(af[mi][0]), "r"(af[mi][1]), "r"(af[mi][2]), "r"(af[mi][3]),
                          "r"(bfr[nj][0]), "r"(bfr[nj][1]));
                }
        }
        cp_commit();                          // one group per kt (uniform count)
    }

    // ---- epilogue: fp32 scores + per-row tile top1/top2 ----
    __syncthreads();                           // staging smem free; reuse it
    float* sv1 = (float*)smem;                 // [2 nwarp][128 rows]
    int*   si1 = (int*)(smem + 1024);
    float* sv2 = (float*)(smem + 2048);
    const int nw = wid >> 2;

#pragma unroll
    for (int mi = 0; mi < 2; ++mi) {
        const int rloc = wm + mi * 16 + (lane >> 2);   // local row (a); row b = +8
        float v1a = -3.4e38f, v2a = -3.4e38f; int i1a = 0;
        float v1b = -3.4e38f, v2b = -3.4e38f; int i1b = 0;
        const int row0 = rowBase + rloc;
#pragma unroll
        for (int nj = 0; nj < 8; ++nj) {
            const int col = nBase + wn + nj * 8 + (lane & 3) * 2;
            float2 bv = *(const float2*)(g_bias + col);
            float s0 = acc[mi][nj][0] + bv.x, s1 = acc[mi][nj][1] + bv.y;
            float s2 = acc[mi][nj][2] + bv.x, s3 = acc[mi][nj][3] + bv.y;
            *(float2*)(g_scores + (size_t)row0 * NMEM + col) = make_float2(s0, s1);
            *(float2*)(g_scores + (size_t)(row0 + 8) * NMEM + col) = make_float2(s2, s3);
            top2upd(s0, col, v1a, i1a, v2a);  top2upd(s1, col + 1, v1a, i1a, v2a);
            top2upd(s2, col, v1b, i1b, v2b);  top2upd(s3, col + 1, v1b, i1b, v2b);
        }
#pragma unroll
        for (int o = 1; o <= 2; o <<= 1) {
            float ov1 = __shfl_xor_sync(0xffffffffu, v1a, o);
            int   oi1 = __shfl_xor_sync(0xffffffffu, i1a, o);
            float ov2 = __shfl_xor_sync(0xffffffffu, v2a, o);
            top2merge(ov1, oi1, ov2, v1a, i1a, v2a);
            ov1 = __shfl_xor_sync(0xffffffffu, v1b, o);
            oi1 = __shfl_xor_sync(0xffffffffu, i1b, o);
            ov2 = __shfl_xor_sync(0xffffffffu, v2b, o);
            top2merge(ov1, oi1, ov2, v1b, i1b, v2b);
        }
        if ((lane & 3) == 0) {
            sv1[nw * 128 + rloc] = v1a; si1[nw * 128 + rloc] = i1a; sv2[nw * 128 + rloc] = v2a;
            sv1[nw * 128 + rloc + 8] = v1b; si1[nw * 128 + rloc + 8] = i1b; sv2[nw * 128 + rloc + 8] = v2b;
        }
    }
    __syncthreads();
    if (tid < 128) {
        float v1 = sv1[tid]; int i1 = si1[tid]; float v2 = sv2[tid];
        top2merge(sv1[128 + tid], si1[128 + tid], sv2[128 + tid], v1, i1, v2);
        g_top[(size_t)(rowBase + tid) * NT + blockIdx.x] =
            make_float4(v1, v2, __int_as_float(i1), 0.f);
    }
}

// ---------------- kernel 4: reduce tile records, decide or collect candidates ----------------
__global__ void k_select(const int* __restrict__ mapping) {
    if (blockIdx.x == 0 && threadIdx.x == 0) g_maxkey = 0u;   // reset for fold
    const int l = (blockIdx.x * blockDim.x + threadIdx.x) >> 5;
    const int lane = threadIdx.x & 31;
    if (l >= L_) return;

    // one lane per N-tile (32 tiles), single 16B load
    float4 rec = g_top[(size_t)l * NT + lane];
    float m1 = rec.x, m2 = rec.y;
    int   i1 = __float_as_int(rec.z);
#pragma unroll
    for (int off = 16; off; off >>= 1) {
        float om1 = __shfl_xor_sync(0xffffffffu, m1, off);
        float om2 = __shfl_xor_sync(0xffffffffu, m2, off);
        int   oi1 = __shfl_xor_sync(0xffffffffu, i1, off);
        top2merge(om1, oi1, om2, m1, i1, m2);
    }

    if (m1 - m2 > MARGIN) {
        if (lane == 0) { g_pid[l] = mapping[i1]; g_candcnt[l] = 1; }
        return;
    }
    // ambiguous: provisional winner first (safety: if collection yields 1, it stands)
    if (lane == 0) g_pid[l] = mapping[i1];

    // collect candidates within MARGIN (fp32 float4 loads, lane-major ascending order)
    const float* row = g_scores + (size_t)l * NMEM;
    const float thr = m1 - MARGIN;
    int base = 0;
    for (int n0 = 0; n0 < NMEM; n0 += 128) {           // 32 lanes x 4 values
        const int n = n0 + lane * 4;
        float4 v4 = *(const float4*)(row + n);
        float v[4] = {v4.x, v4.y, v4.z, v4.w};
        bool p[4]; int cnt = 0;
#pragma unroll
        for (int j = 0; j < 4; ++j) { p[j] = v[j] >= thr; cnt += p[j]; }
        int pre = cnt;
#pragma unroll
        for (int o = 1; o < 32; o <<= 1) {
            int t = __shfl_up_sync(0xffffffffu, pre, o);
            if (lane >= o) pre += t;
        }
        int pos = base + pre - cnt;
#pragma unroll
        for (int j = 0; j < 4; ++j) {
            if (p[j]) {
                if (pos < CMAX) g_cand[(size_t)l * CMAX + pos] = n + j;
                pos++;
            }
        }
        base += __shfl_sync(0xffffffffu, pre, 31);
    }
    if (lane == 0) g_candcnt[l] = base;   // may exceed CMAX -> full rescan
}

// ---------------- kernel 5: exact fp32 rescue for ambiguous patches ----------------
__global__ void k_rescore(const float* __restrict__ image,
                          const float* __restrict__ mem,
                          const int* __restrict__ mapping) {
    const int l = blockIdx.x;
    const int cnt = g_candcnt[l];
    if (cnt <= 1) return;

    __shared__ float sp[D_];     // 12 KB exact patch
    __shared__ float red[4];
    const int lh = l / LWW, lw = l - lh * LWW;
    for (int d = threadIdx.x; d < D_; d += 128) {
        int c = d >> 10, kh = (d >> 5) & 31, kw = d & 31;
        int y = lh + kh - PADP, x = lw + kw - PADP;
        float v = 0.f;
        if ((unsigned)y < HH && (unsigned)x < WW)
            v = image[(y * WW + x) * CC + c];
        sp[d] = v;
    }
    __syncthreads();

    const bool full = cnt > CMAX;
    const int num = full ? NMEM : cnt;
    float best = -3.4e38f;
    int bestn = 0;
    for (int c = 0; c < num; ++c) {
        const int n = full ? c : g_cand[(size_t)l * CMAX + c];
        const float* mrow = mem + (size_t)n * D_;
        float s = 0.f;
        for (int k = threadIdx.x; k < D_; k += 128) s = fmaf(sp[k], mrow[k], s);
#pragma unroll
        for (int o = 16; o; o >>= 1) s += __shfl_xor_sync(0xffffffffu, s, o);
        if ((threadIdx.x & 31) == 0) red[threadIdx.x >> 5] = s;
        __syncthreads();
        if (threadIdx.x == 0) {
            float tot = red[0] + red[1] + red[2] + red[3] + g_bias[n];
            if (tot > best) { best = tot; bestn = n; }   // ascending n -> first max wins
        }
        __syncthreads();
    }
    if (threadIdx.x == 0) g_pid[l] = mapping[bestn];
}

// ---------------- kernel 6: fold (gather) + global max ----------------
__global__ void k_fold(const float* __restrict__ mem2) {
    __shared__ int spid[32 * LWW];
    const int h = blockIdx.x;
    const int c = blockIdx.y;
    const int w = threadIdx.x;               // 0..127

    const int lh0 = max(0, h - (KHH - 1 - PADP));
    const int lh1 = min(LHH - 1, h + PADP);
    const int nrows = lh1 - lh0 + 1;
    for (int idx = threadIdx.x; idx < nrows * LWW; idx += 128)
        spid[idx] = g_pid[(lh0 + idx / LWW) * LWW + idx % LWW];
    __syncthreads();

    float s = 0.f;
#pragma unroll 1
    for (int kh = 0; kh < KHH; ++kh) {
        int lh = h + PADP - kh;
        if (lh < lh0 || lh > lh1) continue;
        const int base = (lh - lh0) * LWW;
        const int rowoff = c * 1024 + kh * 32;
#pragma unroll
        for (int kw = 0; kw < KWW; ++kw) {
            int lw = w + PADP - kw;
            if ((unsigned)lw < LWW) {
                int pid = spid[base + lw];
                s += __ldg(&mem2[(size_t)pid * D_ + rowoff + kw]);
            }
        }
    }
    g_facc[(c * HH + h) * WW + w] = s;

    float m = s;
#pragma unroll
    for (int o = 16; o; o >>= 1) m = fmaxf(m, __shfl_xor_sync(0xffffffffu, m, o));
    __shared__ float wm[4];
    if ((threadIdx.x & 31) == 0) wm[threadIdx.x >> 5] = m;
    __syncthreads();
    if (threadIdx.x == 0) {
        m = fmaxf(fmaxf(wm[0], wm[1]), fmaxf(wm[2], wm[3]));
        unsigned b = __float_as_uint(m);
        unsigned key = (b & 0x80000000u) ? ~b : (b | 0x80000000u);
        atomicMax(&g_maxkey, key);
    }
}

// ---------------- kernel 7: normalize + transpose to (H,W,C) ----------------
__global__ void k_norm(float* __restrict__ out) {
    int i = blockIdx.x * 256 + threadIdx.x;
    if (i >= HH * WW * CC) return;
    unsigned key = g_maxkey;
    unsigned b = (key & 0x80000000u) ? (key & 0x7fffffffu) : ~key;
    float mx = __uint_as_float(b);
    int c = i % CC;
    int w = (i / CC) % WW;
    int h = i / (CC * WW);
    out[i] = g_facc[(c * HH + h) * WW + w] / mx;
}

// ---------------- launcher ----------------
extern "C" void kernel_launch(void* const* d_in, const int* in_sizes, int n_in,
                              void* d_out, int out_size) {
    const float* image   = (const float*)d_in[0];
    const float* mem     = (const float*)d_in[1];
    const float* mem2    = (const float*)d_in[2];
    const int*   mapping = (const int*)d_in[3];
    float* out = (float*)d_out;

    cudaFuncSetAttribute(k_gemm, cudaFuncAttributeMaxDynamicSharedMemorySize, SMEM_GEMM);

    k_prepB<<<NMEM, 128>>>(mem);
    k_im2colA<<<LPAD, 256>>>(image);
    k_gemm<<<dim3(NMEM / TNB, LPAD / TM), 256, SMEM_GEMM>>>();
    k_select<<<(L_ + 7) / 8, 256>>>(mapping);
    k_rescore<<<L_, 128>>>(image, mem, mapping);
    k_fold<<<dim3(HH, CC), 128>>>(mem2);
    k_norm<<<(HH * WW * CC + 255) / 256, 256>>>(out);
}